// round 3
// baseline (speedup 1.0000x reference)
#include <cuda_runtime.h>

#define BB    4
#define NPER  100000
#define NSOL  8
#define NROWS (BB * NPER)
#define GRID  1184          // 148 SMs * 8
#define TPB   256
#define NPART 68            // 32 a_energy + 32 load + 4 vol

// ---------------- device-global scratch (no allocs allowed) ------------------
// Bin-major partials: g_part[row][block]. Rows 0-31: a_energy[b*8+s],
// rows 32-63: load[b*8+s], rows 64-67: vol[b]. Overwritten every run, so no
// init kernel is needed. Ticket counter self-resets in the last block.
__device__ float    g_part[NPART][GRID];
__device__ unsigned g_count;   // zero-initialized at load; reset each run

// ---------------- helpers ----------------------------------------------------
__device__ __forceinline__ void warp_reduce_add(float& v) {
#pragma unroll
    for (int off = 16; off > 0; off >>= 1)
        v += __shfl_xor_sync(0xffffffffu, v, off);
}

// Reduce across lanes of the SAME parity only (offsets 16,8,4,2).
__device__ __forceinline__ void warp_reduce_add_pair(float& v) {
#pragma unroll
    for (int off = 16; off >= 2; off >>= 1)
        v += __shfl_xor_sync(0xffffffffu, v, off);
}

// Static-index compare-chain accumulate of a 4-sol partial into the right batch.
__device__ __forceinline__ void accum4(float (&acc)[BB][4], int r, float tx, float ty,
                                       float tz, float tw) {
    if (r < 2 * NPER) {
        if (r < NPER) { acc[0][0] += tx; acc[0][1] += ty; acc[0][2] += tz; acc[0][3] += tw; }
        else          { acc[1][0] += tx; acc[1][1] += ty; acc[1][2] += tz; acc[1][3] += tw; }
    } else {
        if (r < 3 * NPER) { acc[2][0] += tx; acc[2][1] += ty; acc[2][2] += tz; acc[2][3] += tw; }
        else              { acc[3][0] += tx; acc[3][1] += ty; acc[3][2] += tz; acc[3][3] += tw; }
    }
}

// ---------------- the single fused kernel ------------------------------------
__global__ void __launch_bounds__(TPB)
fused_kernel(const int* __restrict__ ind,      // A_ind as raw 32-bit words
             const float* __restrict__ val,
             const float4* __restrict__ x4,
             const float4* __restrict__ rhs4,
             const float* __restrict__ mass,
             int nnz,
             float* __restrict__ out) {
    __shared__ float sbin[NPART];
    __shared__ float fin[NPART];
    __shared__ int   s_sh;
    __shared__ bool  s_last;

    const int tid  = threadIdx.x;
    const int lane = tid & 31;

    // Detect index dtype per block (cheap: 256B, L2-resident). If A_ind is
    // int64 with values < 2^32, every odd 32-bit word of the first 32 entries
    // is 0; for genuine int32 data P(all zero) ~ (2.5e-6)^32.
    if (tid == 0) {
        int all0 = 1;
#pragma unroll
        for (int k = 0; k < 32; k++)
            if (ind[2 * k + 1] != 0) all0 = 0;
        s_sh = all0;   // shift: 1 if int64 (stride 2 words), 0 if int32
    }
    if (tid < NPART) sbin[tid] = 0.0f;
    __syncthreads();
    const int sh = s_sh;

    // ================= Phase A: per-nnz energy ===============================
    // Lane pairs share one nnz: even lane handles sols 0-3 (x4[2r]), odd lane
    // sols 4-7 (x4[2r+1]); both halves live in the same 128B line -> 2 L1
    // wavefronts per nnz (the floor). Index/val streams are prefetched one
    // iteration ahead to break the idx->x dependency chain.
    float acc[BB][4];
#pragma unroll
    for (int b = 0; b < BB; b++)
#pragma unroll
        for (int s = 0; s < 4; s++) acc[b][s] = 0.0f;

    const int g    = blockIdx.x * TPB + tid;
    const int half = g & 1;                       // lane parity
    const int pstr = (GRID * TPB) >> 1;           // pair stride

    int  i0 = g >> 1;
    int  i1 = i0 + pstr;
    bool h0 = i0 < nnz, h1 = i1 < nnz;
    int  r0 = 0, c0 = 0, r1 = 0, c1 = 0;
    float v0 = 0.0f, v1 = 0.0f;
    if (h0) { r0 = ind[i0 << sh]; c0 = ind[(nnz + i0) << sh]; v0 = val[i0]; }
    if (h1) { r1 = ind[i1 << sh]; c1 = ind[(nnz + i1) << sh]; v1 = val[i1]; }

    while (h0) {
        const int  i2 = i0 + 2 * pstr, i3 = i1 + 2 * pstr;
        const bool h2 = i2 < nnz, h3 = i3 < nnz;
        int  r2 = 0, c2 = 0, r3 = 0, c3 = 0;
        float v2 = 0.0f, v3 = 0.0f;
        if (h2) { r2 = ind[i2 << sh]; c2 = ind[(nnz + i2) << sh]; v2 = val[i2]; }
        if (h3) { r3 = ind[i3 << sh]; c3 = ind[(nnz + i3) << sh]; v3 = val[i3]; }

        float4 a = __ldg(x4 + 2 * r0 + half);
        float4 b = __ldg(x4 + 2 * c0 + half);
        float4 c, d;
        if (h1) {
            c = __ldg(x4 + 2 * r1 + half);
            d = __ldg(x4 + 2 * c1 + half);
        }
        accum4(acc, r0, v0 * a.x * b.x, v0 * a.y * b.y, v0 * a.z * b.z, v0 * a.w * b.w);
        if (h1)
            accum4(acc, r1, v1 * c.x * d.x, v1 * c.y * d.y, v1 * c.z * d.z, v1 * c.w * d.w);

        i0 = i2; i1 = i3; h0 = h2; h1 = h3;
        r0 = r2; c0 = c2; v0 = v2;
        r1 = r3; c1 = c3; v1 = v3;
    }

#pragma unroll
    for (int b = 0; b < BB; b++)
#pragma unroll
        for (int s = 0; s < 4; s++) warp_reduce_add_pair(acc[b][s]);
    if (lane < 2) {
#pragma unroll
        for (int b = 0; b < BB; b++)
#pragma unroll
            for (int s = 0; s < 4; s++)
                atomicAdd(&sbin[b * NSOL + lane * 4 + s], acc[b][s]);
    }

    // ================= Phase B: row stats (load, vol) ========================
    // One row per thread per sweep; warps almost never straddle a batch
    // boundary so the common path is a 9-value same-bin warp reduction.
    const int gs = GRID * TPB;
    for (int ibase = 0; ibase < NROWS; ibase += gs) {
        const int i = ibase + g;
        float t[NSOL] = {0, 0, 0, 0, 0, 0, 0, 0};
        float m = 0.0f;
        int   b = 0;
        if (i < NROWS) {
            m = __ldg(mass + i);
            float4 x0 = __ldg(x4 + 2 * i),   x1 = __ldg(x4 + 2 * i + 1);
            float4 r0f = __ldg(rhs4 + 2 * i), r1f = __ldg(rhs4 + 2 * i + 1);
            t[0] = m * r0f.x * x0.x;  t[1] = m * r0f.y * x0.y;
            t[2] = m * r0f.z * x0.z;  t[3] = m * r0f.w * x0.w;
            t[4] = m * r1f.x * x1.x;  t[5] = m * r1f.y * x1.y;
            t[6] = m * r1f.z * x1.z;  t[7] = m * r1f.w * x1.w;
            b = (i >= NPER) + (i >= 2 * NPER) + (i >= 3 * NPER);
        }
        const int b0 = __shfl_sync(0xffffffffu, b, 0);
        if (__all_sync(0xffffffffu, b == b0)) {
#pragma unroll
            for (int s = 0; s < NSOL; s++) warp_reduce_add(t[s]);
            warp_reduce_add(m);
            if (lane == 0) {
#pragma unroll
                for (int s = 0; s < NSOL; s++) atomicAdd(&sbin[32 + b0 * NSOL + s], t[s]);
                atomicAdd(&sbin[64 + b0], m);
            }
        } else {
#pragma unroll
            for (int s = 0; s < NSOL; s++) atomicAdd(&sbin[32 + b * NSOL + s], t[s]);
            atomicAdd(&sbin[64 + b], m);
        }
    }
    __syncthreads();

    // ================= publish partials, elect last block ====================
    if (tid < NPART) g_part[tid][blockIdx.x] = sbin[tid];
    __threadfence();
    if (tid == 0)
        s_last = (atomicAdd(&g_count, 1u) == (unsigned)(gridDim.x - 1));
    __syncthreads();
    if (!s_last) return;

    // ================= last block: reduce partials + finalize ================
    const int wid = tid >> 5;
    for (int row = wid; row < NPART; row += TPB / 32) {
        float s = 0.0f;
#pragma unroll 4
        for (int j = lane; j < GRID; j += 32) s += g_part[row][j];
        warp_reduce_add(s);
        if (lane == 0) fin[row] = s;
    }
    __syncthreads();

    if (tid < 32) {
        const float ae  = fin[tid];
        const float ld  = fin[32 + tid];
        const float vol = fin[64 + tid / NSOL];

        const float sigma  = ld / fmaxf(ae, 1e-4f);
        float kkt_e  = (0.5f * ae * sigma - ld) * sigma / vol;
        float comp_b = sigma * ld / vol;

        warp_reduce_add(kkt_e);
        warp_reduce_add(comp_b);

        if (tid == 0) {
            const float kkt  = kkt_e / 32.0f;
            const float comp = -(comp_b / 32.0f);
            out[0] = 0.5f * comp + 0.5f * kkt;   // LAMB_COMP = 0.5
            g_count = 0u;                        // reset for next replay
        }
    }
}

// ---------------- launch ------------------------------------------------------
extern "C" void kernel_launch(void* const* d_in, const int* in_sizes, int n_in,
                              void* d_out, int out_size) {
    const float* x     = (const float*)d_in[0];
    const float* rhs   = (const float*)d_in[1];
    const int*   A_ind = (const int*)d_in[2];
    const float* A_val = (const float*)d_in[3];
    // d_in[4] (subspace_vectors) is unused by the reference
    const float* mass  = (const float*)d_in[5];
    const int    nnz   = in_sizes[3];

    fused_kernel<<<GRID, TPB>>>(A_ind, A_val, (const float4*)x, (const float4*)rhs,
                                mass, nnz, (float*)d_out);
}

// round 4
// speedup vs baseline: 1.0024x; 1.0024x over previous
#include <cuda_runtime.h>

#define BB    4
#define NPER  100000
#define NSOL  8
#define NROWS (BB * NPER)
#define GRID  1184          // 148 SMs * 8
#define TPB   256
#define NPART 68            // 32 a_energy + 32 load + 4 vol

// ---------------- device-global scratch (no allocs allowed) ------------------
// Bin-major partials: g_part[row][block]. Rows 0-31: a_energy[b*8+s],
// rows 32-63: load[b*8+s], rows 64-67: vol[b]. Overwritten every run, so no
// init kernel is needed. Ticket counter self-resets in the last block.
__device__ float    g_part[NPART][GRID];
__device__ unsigned g_count;   // zero-initialized at load; reset each run

// ---------------- helpers ----------------------------------------------------
__device__ __forceinline__ void warp_reduce_add(float& v) {
#pragma unroll
    for (int off = 16; off > 0; off >>= 1)
        v += __shfl_xor_sync(0xffffffffu, v, off);
}

// Reduce across lanes of the SAME parity only (offsets 16,8,4,2).
__device__ __forceinline__ void warp_reduce_add_pair(float& v) {
#pragma unroll
    for (int off = 16; off >= 2; off >>= 1)
        v += __shfl_xor_sync(0xffffffffu, v, off);
}

// Static-index compare-chain accumulate of a 4-sol partial into the right batch.
__device__ __forceinline__ void accum4(float (&acc)[BB][4], int r, float tx, float ty,
                                       float tz, float tw) {
    if (r < 2 * NPER) {
        if (r < NPER) { acc[0][0] += tx; acc[0][1] += ty; acc[0][2] += tz; acc[0][3] += tw; }
        else          { acc[1][0] += tx; acc[1][1] += ty; acc[1][2] += tz; acc[1][3] += tw; }
    } else {
        if (r < 3 * NPER) { acc[2][0] += tx; acc[2][1] += ty; acc[2][2] += tz; acc[2][3] += tw; }
        else              { acc[3][0] += tx; acc[3][1] += ty; acc[3][2] += tz; acc[3][3] += tw; }
    }
}

// ---------------- the single fused kernel ------------------------------------
__global__ void __launch_bounds__(TPB)
fused_kernel(const int* __restrict__ ind,      // A_ind as raw 32-bit words
             const float* __restrict__ val,
             const float4* __restrict__ x4,
             const float4* __restrict__ rhs4,
             const float* __restrict__ mass,
             int nnz,
             float* __restrict__ out) {
    __shared__ float sbin[NPART];
    __shared__ float fin[NPART];
    __shared__ int   s_sh;
    __shared__ bool  s_last;

    const int tid  = threadIdx.x;
    const int lane = tid & 31;

    // Detect index dtype per block (cheap: 256B, L2-resident). If A_ind is
    // int64 with values < 2^32, every odd 32-bit word of the first 32 entries
    // is 0; for genuine int32 data P(all zero) ~ (2.5e-6)^32.
    if (tid == 0) {
        int all0 = 1;
#pragma unroll
        for (int k = 0; k < 32; k++)
            if (ind[2 * k + 1] != 0) all0 = 0;
        s_sh = all0;   // shift: 1 if int64 (stride 2 words), 0 if int32
    }
    if (tid < NPART) sbin[tid] = 0.0f;
    __syncthreads();
    const int sh = s_sh;

    // ================= Phase A: per-nnz energy ===============================
    // Lane pairs share one nnz: even lane handles sols 0-3 (x4[2r]), odd lane
    // sols 4-7 (x4[2r+1]); both halves live in the same 128B line -> 2 L1
    // wavefronts per nnz (the floor). Index/val streams are prefetched one
    // iteration ahead to break the idx->x dependency chain.
    float acc[BB][4];
#pragma unroll
    for (int b = 0; b < BB; b++)
#pragma unroll
        for (int s = 0; s < 4; s++) acc[b][s] = 0.0f;

    const int g    = blockIdx.x * TPB + tid;
    const int half = g & 1;                       // lane parity
    const int pstr = (GRID * TPB) >> 1;           // pair stride

    int  i0 = g >> 1;
    int  i1 = i0 + pstr;
    bool h0 = i0 < nnz, h1 = i1 < nnz;
    int  r0 = 0, c0 = 0, r1 = 0, c1 = 0;
    float v0 = 0.0f, v1 = 0.0f;
    if (h0) { r0 = ind[i0 << sh]; c0 = ind[(nnz + i0) << sh]; v0 = val[i0]; }
    if (h1) { r1 = ind[i1 << sh]; c1 = ind[(nnz + i1) << sh]; v1 = val[i1]; }

    while (h0) {
        const int  i2 = i0 + 2 * pstr, i3 = i1 + 2 * pstr;
        const bool h2 = i2 < nnz, h3 = i3 < nnz;
        int  r2 = 0, c2 = 0, r3 = 0, c3 = 0;
        float v2 = 0.0f, v3 = 0.0f;
        if (h2) { r2 = ind[i2 << sh]; c2 = ind[(nnz + i2) << sh]; v2 = val[i2]; }
        if (h3) { r3 = ind[i3 << sh]; c3 = ind[(nnz + i3) << sh]; v3 = val[i3]; }

        float4 a = __ldg(x4 + 2 * r0 + half);
        float4 b = __ldg(x4 + 2 * c0 + half);
        float4 c, d;
        if (h1) {
            c = __ldg(x4 + 2 * r1 + half);
            d = __ldg(x4 + 2 * c1 + half);
        }
        accum4(acc, r0, v0 * a.x * b.x, v0 * a.y * b.y, v0 * a.z * b.z, v0 * a.w * b.w);
        if (h1)
            accum4(acc, r1, v1 * c.x * d.x, v1 * c.y * d.y, v1 * c.z * d.z, v1 * c.w * d.w);

        i0 = i2; i1 = i3; h0 = h2; h1 = h3;
        r0 = r2; c0 = c2; v0 = v2;
        r1 = r3; c1 = c3; v1 = v3;
    }

#pragma unroll
    for (int b = 0; b < BB; b++)
#pragma unroll
        for (int s = 0; s < 4; s++) warp_reduce_add_pair(acc[b][s]);
    if (lane < 2) {
#pragma unroll
        for (int b = 0; b < BB; b++)
#pragma unroll
            for (int s = 0; s < 4; s++)
                atomicAdd(&sbin[b * NSOL + lane * 4 + s], acc[b][s]);
    }

    // ================= Phase B: row stats (load, vol) ========================
    // One row per thread per sweep; warps almost never straddle a batch
    // boundary so the common path is a 9-value same-bin warp reduction.
    const int gs = GRID * TPB;
    for (int ibase = 0; ibase < NROWS; ibase += gs) {
        const int i = ibase + g;
        float t[NSOL] = {0, 0, 0, 0, 0, 0, 0, 0};
        float m = 0.0f;
        int   b = 0;
        if (i < NROWS) {
            m = __ldg(mass + i);
            float4 x0 = __ldg(x4 + 2 * i),   x1 = __ldg(x4 + 2 * i + 1);
            float4 r0f = __ldg(rhs4 + 2 * i), r1f = __ldg(rhs4 + 2 * i + 1);
            t[0] = m * r0f.x * x0.x;  t[1] = m * r0f.y * x0.y;
            t[2] = m * r0f.z * x0.z;  t[3] = m * r0f.w * x0.w;
            t[4] = m * r1f.x * x1.x;  t[5] = m * r1f.y * x1.y;
            t[6] = m * r1f.z * x1.z;  t[7] = m * r1f.w * x1.w;
            b = (i >= NPER) + (i >= 2 * NPER) + (i >= 3 * NPER);
        }
        const int b0 = __shfl_sync(0xffffffffu, b, 0);
        if (__all_sync(0xffffffffu, b == b0)) {
#pragma unroll
            for (int s = 0; s < NSOL; s++) warp_reduce_add(t[s]);
            warp_reduce_add(m);
            if (lane == 0) {
#pragma unroll
                for (int s = 0; s < NSOL; s++) atomicAdd(&sbin[32 + b0 * NSOL + s], t[s]);
                atomicAdd(&sbin[64 + b0], m);
            }
        } else {
#pragma unroll
            for (int s = 0; s < NSOL; s++) atomicAdd(&sbin[32 + b * NSOL + s], t[s]);
            atomicAdd(&sbin[64 + b], m);
        }
    }
    __syncthreads();

    // ================= publish partials, elect last block ====================
    if (tid < NPART) g_part[tid][blockIdx.x] = sbin[tid];
    __threadfence();
    if (tid == 0)
        s_last = (atomicAdd(&g_count, 1u) == (unsigned)(gridDim.x - 1));
    __syncthreads();
    if (!s_last) return;

    // ================= last block: reduce partials + finalize ================
    const int wid = tid >> 5;
    for (int row = wid; row < NPART; row += TPB / 32) {
        float s = 0.0f;
#pragma unroll 4
        for (int j = lane; j < GRID; j += 32) s += g_part[row][j];
        warp_reduce_add(s);
        if (lane == 0) fin[row] = s;
    }
    __syncthreads();

    if (tid < 32) {
        const float ae  = fin[tid];
        const float ld  = fin[32 + tid];
        const float vol = fin[64 + tid / NSOL];

        const float sigma  = ld / fmaxf(ae, 1e-4f);
        float kkt_e  = (0.5f * ae * sigma - ld) * sigma / vol;
        float comp_b = sigma * ld / vol;

        warp_reduce_add(kkt_e);
        warp_reduce_add(comp_b);

        if (tid == 0) {
            const float kkt  = kkt_e / 32.0f;
            const float comp = -(comp_b / 32.0f);
            out[0] = 0.5f * comp + 0.5f * kkt;   // LAMB_COMP = 0.5
            g_count = 0u;                        // reset for next replay
        }
    }
}

// ---------------- launch ------------------------------------------------------
extern "C" void kernel_launch(void* const* d_in, const int* in_sizes, int n_in,
                              void* d_out, int out_size) {
    const float* x     = (const float*)d_in[0];
    const float* rhs   = (const float*)d_in[1];
    const int*   A_ind = (const int*)d_in[2];
    const float* A_val = (const float*)d_in[3];
    // d_in[4] (subspace_vectors) is unused by the reference
    const float* mass  = (const float*)d_in[5];
    const int    nnz   = in_sizes[3];

    fused_kernel<<<GRID, TPB>>>(A_ind, A_val, (const float4*)x, (const float4*)rhs,
                                mass, nnz, (float*)d_out);
}